// round 7
// baseline (speedup 1.0000x reference)
#include <cuda_runtime.h>
#include <cuda_bf16.h>
#include <math.h>

// Problem constants (fixed by the reference).
#define BB 4096
#define TT 100
#define DD 64
#define HH 128
#define BT 32            // batch rows per CTA
#define NTHREADS 256

typedef unsigned long long u64;

// ---------------- f32x2 packed-math helpers (sm_103a) ----------------
__device__ __forceinline__ u64 pack2(float v) {
    u64 r; asm("mov.b64 %0, {%1, %1};" : "=l"(r) : "f"(v)); return r;
}
__device__ __forceinline__ void unpack2(u64 p, float& lo, float& hi) {
    asm("mov.b64 {%0, %1}, %2;" : "=f"(lo), "=f"(hi) : "l"(p));
}
__device__ __forceinline__ void fma2(u64& acc, u64 a, u64 b) {
    asm("fma.rn.f32x2 %0, %1, %2, %0;" : "+l"(acc) : "l"(a), "l"(b));
}
__device__ __forceinline__ u64 fma2v(u64 a, u64 b, u64 c) {
    u64 d; asm("fma.rn.f32x2 %0, %1, %2, %3;" : "=l"(d) : "l"(a), "l"(b), "l"(c)); return d;
}
__device__ __forceinline__ u64 add2(u64 a, u64 b) {
    u64 r; asm("add.rn.f32x2 %0, %1, %2;" : "=l"(r) : "l"(a), "l"(b)); return r;
}

// ---------------- transposed-weight scratch (__device__ globals: allowed) ----------------
__device__ float g_W1t[HH * HH];        // [k][c] = W1[c][k]
__device__ float g_W2t[HH * HH];
__device__ float g_Wmut[HH * HH];
__device__ float g_Wlvt[HH * HH];
__device__ float g_Wiht[DD * 3 * HH];   // [d][c] = W_ih[c][d], row stride 3H
__device__ float g_Whht[HH * 3 * HH];   // [k][c] = W_hh[c][k], row stride 3H

__global__ void prep_kernel(const float* __restrict__ W1, const float* __restrict__ W2,
                            const float* __restrict__ Wih, const float* __restrict__ Whh,
                            const float* __restrict__ Wmu, const float* __restrict__ Wlv) {
    int i = blockIdx.x * blockDim.x + threadIdx.x;
    if (i < HH * HH) {
        int k = i >> 7, c = i & (HH - 1);
        g_W1t[i]  = W1[c * HH + k];
        g_W2t[i]  = W2[c * HH + k];
        g_Wmut[i] = Wmu[c * HH + k];
        g_Wlvt[i] = Wlv[c * HH + k];
    }
    if (i < DD * 3 * HH) {
        int k = i / (3 * HH), c = i % (3 * HH);
        g_Wiht[i] = Wih[c * DD + k];
    }
    if (i < HH * 3 * HH) {
        int k = i / (3 * HH), c = i % (3 * HH);
        g_Whht[i] = Whh[c * HH + k];
    }
}

// ---------------- core 2-row x 8-col dot with f32x2 accumulation ----------------
// acc[i][j] accumulates output columns (c0+2j, c0+2j+1) for rows r0 (i=0), r0+1 (i=1).
// Wt is k-major: Wt[k*WS + c]. Yin row stride = YS. K multiple of 4.
// Activation rows loaded as float4 per 4-k chunk (cuts scalar LDS 4x).
template <int K, int YS, int WS>
__device__ __forceinline__ void dot2x8(const float* __restrict__ Yin, int r0,
                                       const float* __restrict__ Wt, int c0,
                                       u64 acc[2][4]) {
    const float4* y0 = reinterpret_cast<const float4*>(Yin + r0 * YS);
    const float4* y1 = reinterpret_cast<const float4*>(Yin + (r0 + 1) * YS);
#pragma unroll 2
    for (int kc = 0; kc < K / 4; kc++) {
        const float4 v0 = y0[kc];
        const float4 v1 = y1[kc];
        const float a0s[4] = {v0.x, v0.y, v0.z, v0.w};
        const float a1s[4] = {v1.x, v1.y, v1.z, v1.w};
#pragma unroll
        for (int kk = 0; kk < 4; kk++) {
            const int k = 4 * kc + kk;
            u64 a0 = pack2(a0s[kk]);
            u64 a1 = pack2(a1s[kk]);
            const ulonglong2* w = reinterpret_cast<const ulonglong2*>(Wt + k * WS + c0);
            ulonglong2 wa = w[0];
            ulonglong2 wb = w[1];
            fma2(acc[0][0], a0, wa.x); fma2(acc[0][1], a0, wa.y);
            fma2(acc[0][2], a0, wb.x); fma2(acc[0][3], a0, wb.y);
            fma2(acc[1][0], a1, wa.x); fma2(acc[1][1], a1, wa.y);
            fma2(acc[1][2], a1, wb.x); fma2(acc[1][3], a1, wb.y);
        }
    }
}

__device__ __forceinline__ float sigmoidf_(float x) { return 1.0f / (1.0f + expf(-x)); }

// ---------------- shared memory layout (floats) ----------------
#define SM_W1T   0
#define SM_W2T   16384
#define SM_HS    32768
#define SM_YS    36864
#define SM_US    40960
#define SM_XS    45056
#define SM_B1    47104
#define SM_B2    47232
#define SM_BIH   47360
#define SM_BHH   47744
#define SM_DTS   48128
#define SM_TOTAL 48256   // floats -> 193024 bytes

__global__ __launch_bounds__(NTHREADS, 1)
void odernn_kernel(const float* __restrict__ x_seq, const float* __restrict__ t_seq,
                   const float* __restrict__ b1, const float* __restrict__ b2,
                   const float* __restrict__ b_ih, const float* __restrict__ b_hh,
                   const float* __restrict__ b_mu, const float* __restrict__ b_lv,
                   float* __restrict__ out) {
    extern __shared__ float sm[];
    float* W1t  = sm + SM_W1T;
    float* W2t  = sm + SM_W2T;
    float* hs   = sm + SM_HS;
    float* ys   = sm + SM_YS;
    float* us   = sm + SM_US;
    float* xs   = sm + SM_XS;
    float* b1s  = sm + SM_B1;
    float* b2s  = sm + SM_B2;
    float* bihs = sm + SM_BIH;
    float* bhhs = sm + SM_BHH;
    float* dts  = sm + SM_DTS;

    const int tid = threadIdx.x;
    const int bbase = blockIdx.x * BT;
    const int cg = tid & 15;        // column group (8 cols each)
    const int rg = tid >> 4;        // row group (2 rows each)
    const int r0 = 2 * rg;
    const int r1 = r0 + 1;
    const int c0 = 8 * cg;

    // Each thread stages a fixed (row, 8-col) slice of x per step: tid -> row
    // tid>>3 (0..31), cols (tid&7)*8. Coalesced 32B segments per warp.
    const int xrow = tid >> 3;
    const int xcol = (tid & 7) * 8;
    const float* xg = x_seq + (size_t)(bbase + xrow) * (TT * DD) + xcol;

    // ---- init: stage weights/biases, zero h, precompute dt ----
    for (int i = tid; i < HH * HH; i += NTHREADS) { W1t[i] = g_W1t[i]; W2t[i] = g_W2t[i]; }
    for (int i = tid; i < HH; i += NTHREADS) { b1s[i] = b1[i]; b2s[i] = b2[i]; }
    for (int i = tid; i < 3 * HH; i += NTHREADS) { bihs[i] = b_ih[i]; bhhs[i] = b_hh[i]; }
    for (int i = tid; i < BT * HH; i += NTHREADS) hs[i] = 0.0f;
    if (tid < TT) dts[tid] = (tid == 0) ? 0.0f : (t_seq[tid] - t_seq[tid - 1]);
    __syncthreads();

#pragma unroll 1
    for (int t = 0; t < TT; t++) {
        // Issue the x-tile global load NOW (lands during the RK4 phase);
        // store to smem just before the final RK4 barrier, so the GRU's
        // post-barrier reads see it without an exposed LDG->STS stall here.
        float4 xv0, xv1;
        {
            const float4* src = reinterpret_cast<const float4*>(xg + t * DD);
            xv0 = src[0];
            xv1 = src[1];
        }
        const float dt  = dts[t];
        const float sub = dt * 0.25f;

        // ---- RK4 jump: 4 substeps ----
#pragma unroll 1
        for (int s = 0; s < 4; s++) {
            u64 hp[2][4];
#pragma unroll
            for (int i = 0; i < 2; i++) {
                const int r = i ? r1 : r0;
#pragma unroll
                for (int j = 0; j < 4; j++)
                    hp[i][j] = *reinterpret_cast<const u64*>(hs + r * HH + c0 + 2 * j);
            }
            u64 rk[2][4];
#pragma unroll 1
            for (int e = 0; e < 4; e++) {
                const float* Yin = (e == 0) ? hs : ys;
                // GEMM1: u = tanh(Y @ W1^T + b1)
                u64 acc[2][4];
#pragma unroll
                for (int j = 0; j < 4; j++) {
                    u64 bp = *reinterpret_cast<const u64*>(b1s + c0 + 2 * j);
                    acc[0][j] = bp; acc[1][j] = bp;
                }
                dot2x8<HH, HH, HH>(Yin, r0, W1t, c0, acc);
#pragma unroll
                for (int i = 0; i < 2; i++) {
                    const int r = i ? r1 : r0;
#pragma unroll
                    for (int j = 0; j < 4; j++) {
                        float lo, hi; unpack2(acc[i][j], lo, hi);
                        us[r * HH + c0 + 2 * j]     = tanhf(lo);
                        us[r * HH + c0 + 2 * j + 1] = tanhf(hi);
                    }
                }
                __syncthreads();
                // GEMM2: k = u @ W2^T + b2
                u64 kk[2][4];
#pragma unroll
                for (int j = 0; j < 4; j++) {
                    u64 bp = *reinterpret_cast<const u64*>(b2s + c0 + 2 * j);
                    kk[0][j] = bp; kk[1][j] = bp;
                }
                dot2x8<HH, HH, HH>(us, r0, W2t, c0, kk);

                const float wsum  = (e == 1 || e == 2) ? 2.0f : 1.0f;
                const float cstep = (e == 2) ? sub : 0.5f * sub;
                const u64 wp = pack2(wsum);
                const u64 cp = pack2(cstep);
                const u64 fp6 = pack2(sub * (1.0f / 6.0f));
#pragma unroll
                for (int i = 0; i < 2; i++) {
                    const int r = i ? r1 : r0;
#pragma unroll
                    for (int j = 0; j < 4; j++) {
                        rk[i][j] = (e == 0) ? kk[i][j] : fma2v(wp, kk[i][j], rk[i][j]);
                        if (e < 3) {
                            *reinterpret_cast<u64*>(ys + r * HH + c0 + 2 * j) =
                                fma2v(cp, kk[i][j], hp[i][j]);
                        } else {
                            *reinterpret_cast<u64*>(hs + r * HH + c0 + 2 * j) =
                                fma2v(fp6, rk[i][j], hp[i][j]);
                        }
                    }
                }
                // Deposit the prefetched x tile right before the last RK4
                // barrier of the last substep; GRU reads xs after it.
                if (s == 3 && e == 3) {
                    float4* dst = reinterpret_cast<float4*>(xs + xrow * DD + xcol);
                    dst[0] = xv0;
                    dst[1] = xv1;
                }
                __syncthreads();
            }
        }

        // ---- GRU cell ----
        u64 aR[2][4], aZ[2][4], aIN[2][4], aHN[2][4];
#pragma unroll
        for (int j = 0; j < 4; j++) {
            u64 bi0 = *reinterpret_cast<const u64*>(bihs + c0 + 2 * j);
            u64 bh0 = *reinterpret_cast<const u64*>(bhhs + c0 + 2 * j);
            u64 v = add2(bi0, bh0); aR[0][j] = v; aR[1][j] = v;
            u64 bi1 = *reinterpret_cast<const u64*>(bihs + HH + c0 + 2 * j);
            u64 bh1 = *reinterpret_cast<const u64*>(bhhs + HH + c0 + 2 * j);
            v = add2(bi1, bh1); aZ[0][j] = v; aZ[1][j] = v;
            u64 bi2 = *reinterpret_cast<const u64*>(bihs + 2 * HH + c0 + 2 * j);
            aIN[0][j] = bi2; aIN[1][j] = bi2;
            u64 bh2 = *reinterpret_cast<const u64*>(bhhs + 2 * HH + c0 + 2 * j);
            aHN[0][j] = bh2; aHN[1][j] = bh2;
        }
        dot2x8<DD, DD, 3 * HH>(xs, r0, g_Wiht, c0, aR);
        dot2x8<DD, DD, 3 * HH>(xs, r0, g_Wiht, HH + c0, aZ);
        dot2x8<DD, DD, 3 * HH>(xs, r0, g_Wiht, 2 * HH + c0, aIN);
        dot2x8<HH, HH, 3 * HH>(hs, r0, g_Whht, c0, aR);
        dot2x8<HH, HH, 3 * HH>(hs, r0, g_Whht, HH + c0, aZ);
        dot2x8<HH, HH, 3 * HH>(hs, r0, g_Whht, 2 * HH + c0, aHN);

        float hnew[2][8];
#pragma unroll
        for (int i = 0; i < 2; i++) {
            const int r = i ? r1 : r0;
#pragma unroll
            for (int j = 0; j < 4; j++) {
                float rlo, rhi, zlo, zhi, ilo, ihi, nlo, nhi;
                unpack2(aR[i][j], rlo, rhi);
                unpack2(aZ[i][j], zlo, zhi);
                unpack2(aIN[i][j], ilo, ihi);
                unpack2(aHN[i][j], nlo, nhi);
                float rg0 = sigmoidf_(rlo), rg1 = sigmoidf_(rhi);
                float zg0 = sigmoidf_(zlo), zg1 = sigmoidf_(zhi);
                float nn0 = tanhf(ilo + rg0 * nlo);
                float nn1 = tanhf(ihi + rg1 * nhi);
                float h0 = hs[r * HH + c0 + 2 * j];
                float h1 = hs[r * HH + c0 + 2 * j + 1];
                hnew[i][2 * j]     = (1.0f - zg0) * nn0 + zg0 * h0;
                hnew[i][2 * j + 1] = (1.0f - zg1) * nn1 + zg1 * h1;
            }
        }
        __syncthreads();   // all reads of hs done before overwrite
#pragma unroll
        for (int i = 0; i < 2; i++) {
            const int r = i ? r1 : r0;
#pragma unroll
            for (int j = 0; j < 8; j++) hs[r * HH + c0 + j] = hnew[i][j];
        }
        __syncthreads();
    }

    // ---- epilogue: mu = h@Wmu^T + b_mu ; logvar = h@Wlv^T + b_lv ----
    u64 am[2][4], al[2][4];
#pragma unroll
    for (int j = 0; j < 4; j++) {
        u64 bm = *reinterpret_cast<const u64*>(b_mu + c0 + 2 * j);
        am[0][j] = bm; am[1][j] = bm;
        u64 bl = *reinterpret_cast<const u64*>(b_lv + c0 + 2 * j);
        al[0][j] = bl; al[1][j] = bl;
    }
    dot2x8<HH, HH, HH>(hs, r0, g_Wmut, c0, am);
    dot2x8<HH, HH, HH>(hs, r0, g_Wlvt, c0, al);
#pragma unroll
    for (int i = 0; i < 2; i++) {
        const int r = i ? r1 : r0;
        const int gb = (bbase + r) * HH + c0;
#pragma unroll
        for (int j = 0; j < 4; j++) {
            *reinterpret_cast<u64*>(out + gb + 2 * j) = am[i][j];
            *reinterpret_cast<u64*>(out + BB * HH + gb + 2 * j) = al[i][j];
        }
    }
}

extern "C" void kernel_launch(void* const* d_in, const int* in_sizes, int n_in,
                              void* d_out, int out_size) {
    const float* x_seq = (const float*)d_in[0];
    const float* t_seq = (const float*)d_in[1];
    const float* W1    = (const float*)d_in[2];
    const float* b1    = (const float*)d_in[3];
    const float* W2    = (const float*)d_in[4];
    const float* b2    = (const float*)d_in[5];
    const float* W_ih  = (const float*)d_in[6];
    const float* W_hh  = (const float*)d_in[7];
    const float* b_ih  = (const float*)d_in[8];
    const float* b_hh  = (const float*)d_in[9];
    const float* W_mu  = (const float*)d_in[10];
    const float* b_mu  = (const float*)d_in[11];
    const float* W_lv  = (const float*)d_in[12];
    const float* b_lv  = (const float*)d_in[13];
    float* out = (float*)d_out;

    prep_kernel<<<192, 256>>>(W1, W2, W_ih, W_hh, W_mu, W_lv);

    const size_t smem_bytes = (size_t)SM_TOTAL * sizeof(float);
    cudaFuncSetAttribute(odernn_kernel, cudaFuncAttributeMaxDynamicSharedMemorySize,
                         (int)smem_bytes);
    odernn_kernel<<<BB / BT, NTHREADS, smem_bytes>>>(
        x_seq, t_seq, b1, b2, b_ih, b_hh, b_mu, b_lv, out);
}

// round 11
// speedup vs baseline: 1.7744x; 1.7744x over previous
#include <cuda_runtime.h>
#include <cuda_bf16.h>
#include <math.h>

// Problem constants (fixed by the reference).
#define BB 4096
#define TT 100
#define DD 64
#define HH 128
#define BT 32            // batch rows per CTA
#define NTHREADS 256
#define HSS 132          // row stride: 16B-aligned rows, 4-bank step per row
#define XSS 68           // x-tile row stride: 16B-aligned, 4-bank step per row
#define RSP 8            // row-pair offset per thread (banks: 8*HSS % 32 == 0)

typedef unsigned long long u64;

// ---------------- f32x2 packed-math helpers (sm_103a) ----------------
__device__ __forceinline__ u64 pack2(float v) {
    u64 r; asm("mov.b64 %0, {%1, %1};" : "=l"(r) : "f"(v)); return r;
}
__device__ __forceinline__ void unpack2(u64 p, float& lo, float& hi) {
    asm("mov.b64 {%0, %1}, %2;" : "=f"(lo), "=f"(hi) : "l"(p));
}
__device__ __forceinline__ void fma2(u64& acc, u64 a, u64 b) {
    asm("fma.rn.f32x2 %0, %1, %2, %0;" : "+l"(acc) : "l"(a), "l"(b));
}
__device__ __forceinline__ u64 fma2v(u64 a, u64 b, u64 c) {
    u64 d; asm("fma.rn.f32x2 %0, %1, %2, %3;" : "=l"(d) : "l"(a), "l"(b), "l"(c)); return d;
}
__device__ __forceinline__ u64 add2(u64 a, u64 b) {
    u64 r; asm("add.rn.f32x2 %0, %1, %2;" : "=l"(r) : "l"(a), "l"(b)); return r;
}

// ---------------- transposed-weight scratch (__device__ globals: allowed) ----------------
__device__ float g_W1t[HH * HH];        // [k][c] = W1[c][k]
__device__ float g_W2t[HH * HH];
__device__ float g_Wmut[HH * HH];
__device__ float g_Wlvt[HH * HH];
__device__ float g_Wiht[DD * 3 * HH];   // [d][c] = W_ih[c][d], row stride 3H
__device__ float g_Whht[HH * 3 * HH];   // [k][c] = W_hh[c][k], row stride 3H

__global__ void prep_kernel(const float* __restrict__ W1, const float* __restrict__ W2,
                            const float* __restrict__ Wih, const float* __restrict__ Whh,
                            const float* __restrict__ Wmu, const float* __restrict__ Wlv) {
    int i = blockIdx.x * blockDim.x + threadIdx.x;
    if (i < HH * HH) {
        int k = i >> 7, c = i & (HH - 1);
        g_W1t[i]  = W1[c * HH + k];
        g_W2t[i]  = W2[c * HH + k];
        g_Wmut[i] = Wmu[c * HH + k];
        g_Wlvt[i] = Wlv[c * HH + k];
    }
    if (i < DD * 3 * HH) {
        int k = i / (3 * HH), c = i % (3 * HH);
        g_Wiht[i] = Wih[c * DD + k];
    }
    if (i < HH * 3 * HH) {
        int k = i / (3 * HH), c = i % (3 * HH);
        g_Whht[i] = Whh[c * HH + k];
    }
}

// ---------------- core 2-row x 8-col dot with f32x2 accumulation ----------------
// acc[i][j] accumulates output columns (c0+2j, c0+2j+1) for rows r0 (i=0), r0+RSP (i=1).
// Wt is k-major: Wt[k*WS + c]. Yin row stride = YS (mult of 4 -> rows 16B-aligned;
// YS % 32 == 4 -> the 8 rgl-lanes' float4 loads tile all 32 banks conflict-free).
template <int K, int YS, int WS>
__device__ __forceinline__ void dot2x8(const float* __restrict__ Yin, int r0,
                                       const float* __restrict__ Wt, int c0,
                                       u64 acc[2][4]) {
    const float4* y0 = reinterpret_cast<const float4*>(Yin + r0 * YS);
    const float4* y1 = reinterpret_cast<const float4*>(Yin + (r0 + RSP) * YS);
#pragma unroll 2
    for (int kc = 0; kc < K / 4; kc++) {
        const float4 v0 = y0[kc];
        const float4 v1 = y1[kc];
        const float a0s[4] = {v0.x, v0.y, v0.z, v0.w};
        const float a1s[4] = {v1.x, v1.y, v1.z, v1.w};
#pragma unroll
        for (int kk = 0; kk < 4; kk++) {
            const int k = 4 * kc + kk;
            u64 a0 = pack2(a0s[kk]);
            u64 a1 = pack2(a1s[kk]);
            const ulonglong2* w = reinterpret_cast<const ulonglong2*>(Wt + k * WS + c0);
            ulonglong2 wa = w[0];
            ulonglong2 wb = w[1];
            fma2(acc[0][0], a0, wa.x); fma2(acc[0][1], a0, wa.y);
            fma2(acc[0][2], a0, wb.x); fma2(acc[0][3], a0, wb.y);
            fma2(acc[1][0], a1, wa.x); fma2(acc[1][1], a1, wa.y);
            fma2(acc[1][2], a1, wb.x); fma2(acc[1][3], a1, wb.y);
        }
    }
}

__device__ __forceinline__ float sigmoidf_(float x) { return 1.0f / (1.0f + expf(-x)); }

// ---------------- shared memory layout (floats) ----------------
#define SM_W1T   0
#define SM_W2T   16384
#define SM_HS    32768                    // 32 x HSS
#define SM_YS    (SM_HS  + BT * HSS)
#define SM_US    (SM_YS  + BT * HSS)
#define SM_XS    (SM_US  + BT * HSS)      // 32 x XSS
#define SM_B1    (SM_XS  + BT * XSS)
#define SM_B2    (SM_B1  + HH)
#define SM_BIH   (SM_B2  + HH)
#define SM_BHH   (SM_BIH + 3 * HH)
#define SM_DTS   (SM_BHH + 3 * HH)
#define SM_TOTAL (SM_DTS + 128)           // 48768 floats -> 195072 bytes

__global__ __launch_bounds__(NTHREADS, 1)
void odernn_kernel(const float* __restrict__ x_seq, const float* __restrict__ t_seq,
                   const float* __restrict__ b1, const float* __restrict__ b2,
                   const float* __restrict__ b_ih, const float* __restrict__ b_hh,
                   const float* __restrict__ b_mu, const float* __restrict__ b_lv,
                   float* __restrict__ out) {
    extern __shared__ float sm[];
    float* W1t  = sm + SM_W1T;
    float* W2t  = sm + SM_W2T;
    float* hs   = sm + SM_HS;
    float* ys   = sm + SM_YS;
    float* us   = sm + SM_US;
    float* xs   = sm + SM_XS;
    float* b1s  = sm + SM_B1;
    float* b2s  = sm + SM_B2;
    float* bihs = sm + SM_BIH;
    float* bhhs = sm + SM_BHH;
    float* dts  = sm + SM_DTS;

    const int tid = threadIdx.x;
    const int bbase = blockIdx.x * BT;

    // Warp tiling: warp covers 16 rows x 32 cols.
    //   lane: cgl = lane&3 (4 col-groups x 8 cols), rgl = lane>>2 (8 row lanes)
    //   warp: warp_row = w&1 (2 x 16 rows), warp_col = w>>1 (4 x 32 cols)
    // Thread owns rows (r0, r0+8): 132*rgl % 32 == 4*rgl -> activation LDS.128
    // conflict-free; weight LDS.128 lanes at banks 8*cgl+{0..7} -> conflict-free.
    const int lane = tid & 31;
    const int wrp  = tid >> 5;
    const int cgl  = lane & 3;
    const int rgl  = lane >> 2;
    const int c0   = (wrp >> 1) * 32 + cgl * 8;
    const int r0   = (wrp & 1) * 16 + rgl;
    const int r1   = r0 + RSP;

    // x staging: tid -> row tid>>3 (0..31), cols (tid&7)*8. Coalesced 32B/warp.
    const int xrow = tid >> 3;
    const int xcol = (tid & 7) * 8;
    const float* xg = x_seq + (size_t)(bbase + xrow) * (TT * DD) + xcol;

    // ---- init: stage weights/biases, zero h, precompute dt ----
    for (int i = tid; i < HH * HH; i += NTHREADS) { W1t[i] = g_W1t[i]; W2t[i] = g_W2t[i]; }
    for (int i = tid; i < HH; i += NTHREADS) { b1s[i] = b1[i]; b2s[i] = b2[i]; }
    for (int i = tid; i < 3 * HH; i += NTHREADS) { bihs[i] = b_ih[i]; bhhs[i] = b_hh[i]; }
    for (int i = tid; i < BT * HSS; i += NTHREADS) hs[i] = 0.0f;
    if (tid < TT) dts[tid] = (tid == 0) ? 0.0f : (t_seq[tid] - t_seq[tid - 1]);
    __syncthreads();

#pragma unroll 1
    for (int t = 0; t < TT; t++) {
        // Issue the x-tile global load NOW (lands during the RK4 phase);
        // deposit to smem just before the final RK4 barrier.
        float4 xv0, xv1;
        {
            const float4* src = reinterpret_cast<const float4*>(xg + t * DD);
            xv0 = src[0];
            xv1 = src[1];
        }
        const float dt  = dts[t];
        const float sub = dt * 0.25f;

        // ---- RK4 jump: 4 substeps ----
#pragma unroll 1
        for (int s = 0; s < 4; s++) {
            u64 hp[2][4];
#pragma unroll
            for (int i = 0; i < 2; i++) {
                const int r = i ? r1 : r0;
#pragma unroll
                for (int j = 0; j < 4; j++)
                    hp[i][j] = *reinterpret_cast<const u64*>(hs + r * HSS + c0 + 2 * j);
            }
            u64 rk[2][4];
#pragma unroll 1
            for (int e = 0; e < 4; e++) {
                const float* Yin = (e == 0) ? hs : ys;
                // GEMM1: u = tanh(Y @ W1^T + b1)
                u64 acc[2][4];
#pragma unroll
                for (int j = 0; j < 4; j++) {
                    u64 bp = *reinterpret_cast<const u64*>(b1s + c0 + 2 * j);
                    acc[0][j] = bp; acc[1][j] = bp;
                }
                dot2x8<HH, HSS, HH>(Yin, r0, W1t, c0, acc);
#pragma unroll
                for (int i = 0; i < 2; i++) {
                    const int r = i ? r1 : r0;
#pragma unroll
                    for (int j = 0; j < 4; j++) {
                        float lo, hi; unpack2(acc[i][j], lo, hi);
                        us[r * HSS + c0 + 2 * j]     = tanhf(lo);
                        us[r * HSS + c0 + 2 * j + 1] = tanhf(hi);
                    }
                }
                __syncthreads();
                // GEMM2: k = u @ W2^T + b2
                u64 kk[2][4];
#pragma unroll
                for (int j = 0; j < 4; j++) {
                    u64 bp = *reinterpret_cast<const u64*>(b2s + c0 + 2 * j);
                    kk[0][j] = bp; kk[1][j] = bp;
                }
                dot2x8<HH, HSS, HH>(us, r0, W2t, c0, kk);

                const float wsum  = (e == 1 || e == 2) ? 2.0f : 1.0f;
                const float cstep = (e == 2) ? sub : 0.5f * sub;
                const u64 wp = pack2(wsum);
                const u64 cp = pack2(cstep);
                const u64 fp6 = pack2(sub * (1.0f / 6.0f));
#pragma unroll
                for (int i = 0; i < 2; i++) {
                    const int r = i ? r1 : r0;
#pragma unroll
                    for (int j = 0; j < 4; j++) {
                        rk[i][j] = (e == 0) ? kk[i][j] : fma2v(wp, kk[i][j], rk[i][j]);
                        if (e < 3) {
                            *reinterpret_cast<u64*>(ys + r * HSS + c0 + 2 * j) =
                                fma2v(cp, kk[i][j], hp[i][j]);
                        } else {
                            *reinterpret_cast<u64*>(hs + r * HSS + c0 + 2 * j) =
                                fma2v(fp6, rk[i][j], hp[i][j]);
                        }
                    }
                }
                // Deposit the prefetched x tile before the last RK4 barrier.
                if (s == 3 && e == 3) {
                    float4* dst = reinterpret_cast<float4*>(xs + xrow * XSS + xcol);
                    dst[0] = xv0;
                    dst[1] = xv1;
                }
                __syncthreads();
            }
        }

        // ---- GRU cell ----
        u64 aR[2][4], aZ[2][4], aIN[2][4], aHN[2][4];
#pragma unroll
        for (int j = 0; j < 4; j++) {
            u64 bi0 = *reinterpret_cast<const u64*>(bihs + c0 + 2 * j);
            u64 bh0 = *reinterpret_cast<const u64*>(bhhs + c0 + 2 * j);
            u64 v = add2(bi0, bh0); aR[0][j] = v; aR[1][j] = v;
            u64 bi1 = *reinterpret_cast<const u64*>(bihs + HH + c0 + 2 * j);
            u64 bh1 = *reinterpret_cast<const u64*>(bhhs + HH + c0 + 2 * j);
            v = add2(bi1, bh1); aZ[0][j] = v; aZ[1][j] = v;
            u64 bi2 = *reinterpret_cast<const u64*>(bihs + 2 * HH + c0 + 2 * j);
            aIN[0][j] = bi2; aIN[1][j] = bi2;
            u64 bh2 = *reinterpret_cast<const u64*>(bhhs + 2 * HH + c0 + 2 * j);
            aHN[0][j] = bh2; aHN[1][j] = bh2;
        }
        dot2x8<DD, XSS, 3 * HH>(xs, r0, g_Wiht, c0, aR);
        dot2x8<DD, XSS, 3 * HH>(xs, r0, g_Wiht, HH + c0, aZ);
        dot2x8<DD, XSS, 3 * HH>(xs, r0, g_Wiht, 2 * HH + c0, aIN);
        dot2x8<HH, HSS, 3 * HH>(hs, r0, g_Whht, c0, aR);
        dot2x8<HH, HSS, 3 * HH>(hs, r0, g_Whht, HH + c0, aZ);
        dot2x8<HH, HSS, 3 * HH>(hs, r0, g_Whht, 2 * HH + c0, aHN);

        float hnew[2][8];
#pragma unroll
        for (int i = 0; i < 2; i++) {
            const int r = i ? r1 : r0;
#pragma unroll
            for (int j = 0; j < 4; j++) {
                float rlo, rhi, zlo, zhi, ilo, ihi, nlo, nhi;
                unpack2(aR[i][j], rlo, rhi);
                unpack2(aZ[i][j], zlo, zhi);
                unpack2(aIN[i][j], ilo, ihi);
                unpack2(aHN[i][j], nlo, nhi);
                float rg0 = sigmoidf_(rlo), rg1 = sigmoidf_(rhi);
                float zg0 = sigmoidf_(zlo), zg1 = sigmoidf_(zhi);
                float nn0 = tanhf(ilo + rg0 * nlo);
                float nn1 = tanhf(ihi + rg1 * nhi);
                float h0 = hs[r * HSS + c0 + 2 * j];
                float h1 = hs[r * HSS + c0 + 2 * j + 1];
                hnew[i][2 * j]     = (1.0f - zg0) * nn0 + zg0 * h0;
                hnew[i][2 * j + 1] = (1.0f - zg1) * nn1 + zg1 * h1;
            }
        }
        __syncthreads();   // all reads of hs done before overwrite
#pragma unroll
        for (int i = 0; i < 2; i++) {
            const int r = i ? r1 : r0;
#pragma unroll
            for (int j = 0; j < 8; j++) hs[r * HSS + c0 + j] = hnew[i][j];
        }
        __syncthreads();
    }

    // ---- epilogue: mu = h@Wmu^T + b_mu ; logvar = h@Wlv^T + b_lv ----
    u64 am[2][4], al[2][4];
#pragma unroll
    for (int j = 0; j < 4; j++) {
        u64 bm = *reinterpret_cast<const u64*>(b_mu + c0 + 2 * j);
        am[0][j] = bm; am[1][j] = bm;
        u64 bl = *reinterpret_cast<const u64*>(b_lv + c0 + 2 * j);
        al[0][j] = bl; al[1][j] = bl;
    }
    dot2x8<HH, HSS, HH>(hs, r0, g_Wmut, c0, am);
    dot2x8<HH, HSS, HH>(hs, r0, g_Wlvt, c0, al);
#pragma unroll
    for (int i = 0; i < 2; i++) {
        const int r = i ? r1 : r0;
        const int gb = (bbase + r) * HH + c0;
#pragma unroll
        for (int j = 0; j < 4; j++) {
            *reinterpret_cast<u64*>(out + gb + 2 * j) = am[i][j];
            *reinterpret_cast<u64*>(out + BB * HH + gb + 2 * j) = al[i][j];
        }
    }
}

extern "C" void kernel_launch(void* const* d_in, const int* in_sizes, int n_in,
                              void* d_out, int out_size) {
    const float* x_seq = (const float*)d_in[0];
    const float* t_seq = (const float*)d_in[1];
    const float* W1    = (const float*)d_in[2];
    const float* b1    = (const float*)d_in[3];
    const float* W2    = (const float*)d_in[4];
    const float* b2    = (const float*)d_in[5];
    const float* W_ih  = (const float*)d_in[6];
    const float* W_hh  = (const float*)d_in[7];
    const float* b_ih  = (const float*)d_in[8];
    const float* b_hh  = (const float*)d_in[9];
    const float* W_mu  = (const float*)d_in[10];
    const float* b_mu  = (const float*)d_in[11];
    const float* W_lv  = (const float*)d_in[12];
    const float* b_lv  = (const float*)d_in[13];
    float* out = (float*)d_out;

    prep_kernel<<<192, 256>>>(W1, W2, W_ih, W_hh, W_mu, W_lv);

    const size_t smem_bytes = (size_t)SM_TOTAL * sizeof(float);
    cudaFuncSetAttribute(odernn_kernel, cudaFuncAttributeMaxDynamicSharedMemorySize,
                         (int)smem_bytes);
    odernn_kernel<<<BB / BT, NTHREADS, smem_bytes>>>(
        x_seq, t_seq, b1, b2, b_ih, b_hh, b_mu, b_lv, out);
}

// round 17
// speedup vs baseline: 2.1721x; 1.2241x over previous
#include <cuda_runtime.h>
#include <cuda_bf16.h>
#include <math.h>

// Problem constants (fixed by the reference).
#define BB 4096
#define TT 100
#define DD 64
#define HH 128
#define BT 32            // batch rows per CTA
#define NTHREADS 128     // 4 warps; thread tile = 4 rows x 8 cols
#define HSS 132          // row stride: 16B-aligned rows, 4-bank step per row
#define XSS 68           // x-tile row stride: 16B-aligned, 4-bank step per row

typedef unsigned long long u64;

// ---------------- f32x2 packed-math helpers (sm_103a) ----------------
__device__ __forceinline__ u64 pack2(float v) {
    u64 r; asm("mov.b64 %0, {%1, %1};" : "=l"(r) : "f"(v)); return r;
}
__device__ __forceinline__ u64 pack2v(float lo, float hi) {
    u64 r; asm("mov.b64 %0, {%1, %2};" : "=l"(r) : "f"(lo), "f"(hi)); return r;
}
__device__ __forceinline__ void unpack2(u64 p, float& lo, float& hi) {
    asm("mov.b64 {%0, %1}, %2;" : "=f"(lo), "=f"(hi) : "l"(p));
}
__device__ __forceinline__ void fma2(u64& acc, u64 a, u64 b) {
    asm("fma.rn.f32x2 %0, %1, %2, %0;" : "+l"(acc) : "l"(a), "l"(b));
}
__device__ __forceinline__ u64 fma2v(u64 a, u64 b, u64 c) {
    u64 d; asm("fma.rn.f32x2 %0, %1, %2, %3;" : "=l"(d) : "l"(a), "l"(b), "l"(c)); return d;
}
__device__ __forceinline__ u64 add2(u64 a, u64 b) {
    u64 r; asm("add.rn.f32x2 %0, %1, %2;" : "=l"(r) : "l"(a), "l"(b)); return r;
}

// ---------------- transposed-weight scratch (__device__ globals: allowed) ----------------
__device__ float g_W1t[HH * HH];        // [k][c] = W1[c][k]
__device__ float g_W2t[HH * HH];
__device__ float g_Wmut[HH * HH];
__device__ float g_Wlvt[HH * HH];
__device__ float g_Wiht[DD * 3 * HH];   // [d][c] = W_ih[c][d], row stride 3H
__device__ float g_Whht[HH * 3 * HH];   // [k][c] = W_hh[c][k], row stride 3H

__global__ void prep_kernel(const float* __restrict__ W1, const float* __restrict__ W2,
                            const float* __restrict__ Wih, const float* __restrict__ Whh,
                            const float* __restrict__ Wmu, const float* __restrict__ Wlv) {
    int i = blockIdx.x * blockDim.x + threadIdx.x;
    if (i < HH * HH) {
        int k = i >> 7, c = i & (HH - 1);
        g_W1t[i]  = W1[c * HH + k];
        g_W2t[i]  = W2[c * HH + k];
        g_Wmut[i] = Wmu[c * HH + k];
        g_Wlvt[i] = Wlv[c * HH + k];
    }
    if (i < DD * 3 * HH) {
        int k = i / (3 * HH), c = i % (3 * HH);
        g_Wiht[i] = Wih[c * DD + k];
    }
    if (i < HH * 3 * HH) {
        int k = i / (3 * HH), c = i % (3 * HH);
        g_Whht[i] = Whh[c * HH + k];
    }
}

// ---------------- core 4-row x 8-col dot with f32x2 accumulation ----------------
// acc[m][j] accumulates output columns (c0+2j, c0+2j+1) for row r0 + 8m.
// Wt is k-major: Wt[k*WS + c]. Yin row stride YS: YS%4==0 (16B rows), YS%32==4
// (rgl lanes tile banks {0,4,...,28}); 8-row offset = 0 bank shift.
template <int K, int YS, int WS>
__device__ __forceinline__ void dot4x8(const float* __restrict__ Yin, int r0,
                                       const float* __restrict__ Wt, int c0,
                                       u64 acc[4][4]) {
    const float4* y0 = reinterpret_cast<const float4*>(Yin + r0 * YS);
    const float4* y1 = reinterpret_cast<const float4*>(Yin + (r0 + 8) * YS);
    const float4* y2 = reinterpret_cast<const float4*>(Yin + (r0 + 16) * YS);
    const float4* y3 = reinterpret_cast<const float4*>(Yin + (r0 + 24) * YS);
#pragma unroll 2
    for (int kc = 0; kc < K / 4; kc++) {
        float4 v[4];
        v[0] = y0[kc]; v[1] = y1[kc]; v[2] = y2[kc]; v[3] = y3[kc];
        const float a0[4] = {v[0].x, v[0].y, v[0].z, v[0].w};
        const float a1[4] = {v[1].x, v[1].y, v[1].z, v[1].w};
        const float a2[4] = {v[2].x, v[2].y, v[2].z, v[2].w};
        const float a3[4] = {v[3].x, v[3].y, v[3].z, v[3].w};
#pragma unroll
        for (int kk = 0; kk < 4; kk++) {
            const int k = 4 * kc + kk;
            const ulonglong2* w = reinterpret_cast<const ulonglong2*>(Wt + k * WS + c0);
            ulonglong2 wa = w[0];
            ulonglong2 wb = w[1];
            u64 p0 = pack2(a0[kk]);
            u64 p1 = pack2(a1[kk]);
            u64 p2 = pack2(a2[kk]);
            u64 p3 = pack2(a3[kk]);
            fma2(acc[0][0], p0, wa.x); fma2(acc[0][1], p0, wa.y);
            fma2(acc[0][2], p0, wb.x); fma2(acc[0][3], p0, wb.y);
            fma2(acc[1][0], p1, wa.x); fma2(acc[1][1], p1, wa.y);
            fma2(acc[1][2], p1, wb.x); fma2(acc[1][3], p1, wb.y);
            fma2(acc[2][0], p2, wa.x); fma2(acc[2][1], p2, wa.y);
            fma2(acc[2][2], p2, wb.x); fma2(acc[2][3], p2, wb.y);
            fma2(acc[3][0], p3, wa.x); fma2(acc[3][1], p3, wa.y);
            fma2(acc[3][2], p3, wb.x); fma2(acc[3][3], p3, wb.y);
        }
    }
}

__device__ __forceinline__ float sigmoidf_(float x) { return 1.0f / (1.0f + expf(-x)); }

// ---------------- shared memory layout (floats) ----------------
#define SM_W1T   0
#define SM_W2T   16384
#define SM_HS    32768                    // 32 x HSS
#define SM_YS    (SM_HS  + BT * HSS)
#define SM_US    (SM_YS  + BT * HSS)
#define SM_XS    (SM_US  + BT * HSS)      // 32 x XSS
#define SM_B1    (SM_XS  + BT * XSS)
#define SM_B2    (SM_B1  + HH)
#define SM_BIH   (SM_B2  + HH)
#define SM_BHH   (SM_BIH + 3 * HH)
#define SM_DTS   (SM_BHH + 3 * HH)
#define SM_TOTAL (SM_DTS + 128)           // 48768 floats -> 195072 bytes

__global__ __launch_bounds__(NTHREADS, 1)
void odernn_kernel(const float* __restrict__ x_seq, const float* __restrict__ t_seq,
                   const float* __restrict__ b1, const float* __restrict__ b2,
                   const float* __restrict__ b_ih, const float* __restrict__ b_hh,
                   const float* __restrict__ b_mu, const float* __restrict__ b_lv,
                   float* __restrict__ out) {
    extern __shared__ float sm[];
    float* W1t  = sm + SM_W1T;
    float* W2t  = sm + SM_W2T;
    float* hs   = sm + SM_HS;
    float* ys   = sm + SM_YS;
    float* us   = sm + SM_US;
    float* xs   = sm + SM_XS;
    float* b1s  = sm + SM_B1;
    float* b2s  = sm + SM_B2;
    float* bihs = sm + SM_BIH;
    float* bhhs = sm + SM_BHH;
    float* dts  = sm + SM_DTS;

    const int tid = threadIdx.x;
    const int bbase = blockIdx.x * BT;

    // Tiling: 4 warps; warp w owns cols 32w..32w+31, ALL 32 rows.
    //   lane: cgl = lane&3 (8-col group), rgl = lane>>2 -> rows {rgl, rgl+8, rgl+16, rgl+24}
    // Weight LDS.128: lanes at banks 8*cgl+{0..7} -> conflict-free.
    // Activation LDS.128: rgl lanes at banks 4*rgl -> conflict-free; +8-row offset = 0 shift.
    const int lane = tid & 31;
    const int wrp  = tid >> 5;
    const int cgl  = lane & 3;
    const int rgl  = lane >> 2;
    const int c0   = wrp * 32 + cgl * 8;
    const int r0   = rgl;

    // x staging: tid -> row tid>>2 (0..31), cols (tid&3)*16 (4 float4).
    const int xrow = tid >> 2;
    const int xcol = (tid & 3) * 16;
    const float* xg = x_seq + (size_t)(bbase + xrow) * (TT * DD) + xcol;

    // ---- init: stage weights/biases, zero h, precompute dt ----
    for (int i = tid; i < HH * HH; i += NTHREADS) { W1t[i] = g_W1t[i]; W2t[i] = g_W2t[i]; }
    for (int i = tid; i < HH; i += NTHREADS) { b1s[i] = b1[i]; b2s[i] = b2[i]; }
    for (int i = tid; i < 3 * HH; i += NTHREADS) { bihs[i] = b_ih[i]; bhhs[i] = b_hh[i]; }
    for (int i = tid; i < BT * HSS; i += NTHREADS) hs[i] = 0.0f;
    if (tid < TT) dts[tid] = (tid == 0) ? 0.0f : (t_seq[tid] - t_seq[tid - 1]);
    __syncthreads();

#pragma unroll 1
    for (int t = 0; t < TT; t++) {
        // Prefetch x tile (lands during RK4); deposited before last RK4 barrier.
        float4 xv[4];
        {
            const float4* src = reinterpret_cast<const float4*>(xg + t * DD);
            xv[0] = src[0]; xv[1] = src[1]; xv[2] = src[2]; xv[3] = src[3];
        }
        const float dt  = dts[t];
        const float sub = dt * 0.25f;

        // ---- RK4 jump: 4 substeps ----
#pragma unroll 1
        for (int s = 0; s < 4; s++) {
            u64 rk[4][4];
#pragma unroll 1
            for (int e = 0; e < 4; e++) {
                const float* Yin = (e == 0) ? hs : ys;
                // GEMM1: u = tanh(Y @ W1^T + b1)
                u64 acc[4][4];
#pragma unroll
                for (int j = 0; j < 4; j++) {
                    u64 bp = *reinterpret_cast<const u64*>(b1s + c0 + 2 * j);
                    acc[0][j] = bp; acc[1][j] = bp; acc[2][j] = bp; acc[3][j] = bp;
                }
                dot4x8<HH, HSS, HH>(Yin, r0, W1t, c0, acc);
#pragma unroll
                for (int m = 0; m < 4; m++) {
                    const int r = r0 + 8 * m;
#pragma unroll
                    for (int j = 0; j < 4; j++) {
                        float lo, hi; unpack2(acc[m][j], lo, hi);
                        *reinterpret_cast<u64*>(us + r * HSS + c0 + 2 * j) =
                            pack2v(tanhf(lo), tanhf(hi));
                    }
                }
                __syncthreads();
                // GEMM2: k = u @ W2^T + b2
                u64 kk[4][4];
#pragma unroll
                for (int j = 0; j < 4; j++) {
                    u64 bp = *reinterpret_cast<const u64*>(b2s + c0 + 2 * j);
                    kk[0][j] = bp; kk[1][j] = bp; kk[2][j] = bp; kk[3][j] = bp;
                }
                dot4x8<HH, HSS, HH>(us, r0, W2t, c0, kk);

                const float wsum  = (e == 1 || e == 2) ? 2.0f : 1.0f;
                const float cstep = (e == 2) ? sub : 0.5f * sub;
                const u64 wp = pack2(wsum);
                const u64 cp = pack2(cstep);
                const u64 fp6 = pack2(sub * (1.0f / 6.0f));
                // hs is stable within the substep; read own h elements on the fly.
#pragma unroll
                for (int m = 0; m < 4; m++) {
                    const int r = r0 + 8 * m;
#pragma unroll
                    for (int j = 0; j < 4; j++) {
                        u64 hv = *reinterpret_cast<const u64*>(hs + r * HSS + c0 + 2 * j);
                        rk[m][j] = (e == 0) ? kk[m][j] : fma2v(wp, kk[m][j], rk[m][j]);
                        if (e < 3) {
                            *reinterpret_cast<u64*>(ys + r * HSS + c0 + 2 * j) =
                                fma2v(cp, kk[m][j], hv);
                        } else {
                            *reinterpret_cast<u64*>(hs + r * HSS + c0 + 2 * j) =
                                fma2v(fp6, rk[m][j], hv);
                        }
                    }
                }
                // Deposit the prefetched x tile before the last RK4 barrier.
                if (s == 3 && e == 3) {
                    float4* dst = reinterpret_cast<float4*>(xs + xrow * XSS + xcol);
                    dst[0] = xv[0]; dst[1] = xv[1]; dst[2] = xv[2]; dst[3] = xv[3];
                }
                __syncthreads();
            }
        }

        // ---- GRU cell (gate-split to cap registers) ----
        // Pass A: r and z gates -> parked in ys (r) and us (z); own elements only.
        {
            u64 aR[4][4], aZ[4][4];
#pragma unroll
            for (int j = 0; j < 4; j++) {
                u64 v = add2(*reinterpret_cast<const u64*>(bihs + c0 + 2 * j),
                             *reinterpret_cast<const u64*>(bhhs + c0 + 2 * j));
                aR[0][j] = v; aR[1][j] = v; aR[2][j] = v; aR[3][j] = v;
                u64 w = add2(*reinterpret_cast<const u64*>(bihs + HH + c0 + 2 * j),
                             *reinterpret_cast<const u64*>(bhhs + HH + c0 + 2 * j));
                aZ[0][j] = w; aZ[1][j] = w; aZ[2][j] = w; aZ[3][j] = w;
            }
            dot4x8<DD, XSS, 3 * HH>(xs, r0, g_Wiht, c0, aR);
            dot4x8<HH, HSS, 3 * HH>(hs, r0, g_Whht, c0, aR);
            dot4x8<DD, XSS, 3 * HH>(xs, r0, g_Wiht, HH + c0, aZ);
            dot4x8<HH, HSS, 3 * HH>(hs, r0, g_Whht, HH + c0, aZ);
#pragma unroll
            for (int m = 0; m < 4; m++) {
                const int r = r0 + 8 * m;
#pragma unroll
                for (int j = 0; j < 4; j++) {
                    float rlo, rhi, zlo, zhi;
                    unpack2(aR[m][j], rlo, rhi);
                    unpack2(aZ[m][j], zlo, zhi);
                    *reinterpret_cast<u64*>(ys + r * HSS + c0 + 2 * j) =
                        pack2v(sigmoidf_(rlo), sigmoidf_(rhi));
                    *reinterpret_cast<u64*>(us + r * HSS + c0 + 2 * j) =
                        pack2v(sigmoidf_(zlo), sigmoidf_(zhi));
                }
            }
        }
        // Pass B: candidate n and state update.
        {
            u64 aI[4][4], aN[4][4];
#pragma unroll
            for (int j = 0; j < 4; j++) {
                u64 v = *reinterpret_cast<const u64*>(bihs + 2 * HH + c0 + 2 * j);
                aI[0][j] = v; aI[1][j] = v; aI[2][j] = v; aI[3][j] = v;
                u64 w = *reinterpret_cast<const u64*>(bhhs + 2 * HH + c0 + 2 * j);
                aN[0][j] = w; aN[1][j] = w; aN[2][j] = w; aN[3][j] = w;
            }
            dot4x8<DD, XSS, 3 * HH>(xs, r0, g_Wiht, 2 * HH + c0, aI);
            dot4x8<HH, HSS, 3 * HH>(hs, r0, g_Whht, 2 * HH + c0, aN);

            u64 hnew[4][4];
#pragma unroll
            for (int m = 0; m < 4; m++) {
                const int r = r0 + 8 * m;
#pragma unroll
                for (int j = 0; j < 4; j++) {
                    float ilo, ihi, nlo, nhi, rlo, rhi, zlo, zhi, hlo, hhi;
                    unpack2(aI[m][j], ilo, ihi);
                    unpack2(aN[m][j], nlo, nhi);
                    unpack2(*reinterpret_cast<const u64*>(ys + r * HSS + c0 + 2 * j), rlo, rhi);
                    unpack2(*reinterpret_cast<const u64*>(us + r * HSS + c0 + 2 * j), zlo, zhi);
                    unpack2(*reinterpret_cast<const u64*>(hs + r * HSS + c0 + 2 * j), hlo, hhi);
                    float nn0 = tanhf(ilo + rlo * nlo);
                    float nn1 = tanhf(ihi + rhi * nhi);
                    hnew[m][j] = pack2v((1.0f - zlo) * nn0 + zlo * hlo,
                                        (1.0f - zhi) * nn1 + zhi * hhi);
                }
            }
            __syncthreads();   // all cross-thread hs reads done before overwrite
#pragma unroll
            for (int m = 0; m < 4; m++) {
                const int r = r0 + 8 * m;
#pragma unroll
                for (int j = 0; j < 4; j++)
                    *reinterpret_cast<u64*>(hs + r * HSS + c0 + 2 * j) = hnew[m][j];
            }
            __syncthreads();
        }
    }

    // ---- epilogue: mu then logvar (sequential to cap registers) ----
    {
        u64 am[4][4];
#pragma unroll
        for (int j = 0; j < 4; j++) {
            u64 bm = *reinterpret_cast<const u64*>(b_mu + c0 + 2 * j);
            am[0][j] = bm; am[1][j] = bm; am[2][j] = bm; am[3][j] = bm;
        }
        dot4x8<HH, HSS, HH>(hs, r0, g_Wmut, c0, am);
#pragma unroll
        for (int m = 0; m < 4; m++) {
            const int gb = (bbase + r0 + 8 * m) * HH + c0;
#pragma unroll
            for (int j = 0; j < 4; j++)
                *reinterpret_cast<u64*>(out + gb + 2 * j) = am[m][j];
        }
    }
    {
        u64 al[4][4];
#pragma unroll
        for (int j = 0; j < 4; j++) {
            u64 bl = *reinterpret_cast<const u64*>(b_lv + c0 + 2 * j);
            al[0][j] = bl; al[1][j] = bl; al[2][j] = bl; al[3][j] = bl;
        }
        dot4x8<HH, HSS, HH>(hs, r0, g_Wlvt, c0, al);
#pragma unroll
        for (int m = 0; m < 4; m++) {
            const int gb = BB * HH + (bbase + r0 + 8 * m) * HH + c0;
#pragma unroll
            for (int j = 0; j < 4; j++)
                *reinterpret_cast<u64*>(out + gb + 2 * j) = al[m][j];
        }
    }
}

extern "C" void kernel_launch(void* const* d_in, const int* in_sizes, int n_in,
                              void* d_out, int out_size) {
    const float* x_seq = (const float*)d_in[0];
    const float* t_seq = (const float*)d_in[1];
    const float* W1    = (const float*)d_in[2];
    const float* b1    = (const float*)d_in[3];
    const float* W2    = (const float*)d_in[4];
    const float* b2    = (const float*)d_in[5];
    const float* W_ih  = (const float*)d_in[6];
    const float* W_hh  = (const float*)d_in[7];
    const float* b_ih  = (const float*)d_in[8];
    const float* b_hh  = (const float*)d_in[9];
    const float* W_mu  = (const float*)d_in[10];
    const float* b_mu  = (const float*)d_in[11];
    const float* W_lv  = (const float*)d_in[12];
    const float* b_lv  = (const float*)d_in[13];
    float* out = (float*)d_out;

    prep_kernel<<<192, 256>>>(W1, W2, W_ih, W_hh, W_mu, W_lv);

    const size_t smem_bytes = (size_t)SM_TOTAL * sizeof(float);
    cudaFuncSetAttribute(odernn_kernel, cudaFuncAttributeMaxDynamicSharedMemorySize,
                         (int)smem_bytes);
    odernn_kernel<<<BB / BT, NTHREADS, smem_bytes>>>(
        x_seq, t_seq, b1, b2, b_ih, b_hh, b_mu, b_lv, out);
}